// round 11
// baseline (speedup 1.0000x reference)
#include <cuda_runtime.h>
#include <cstdint>

#define Nn 50000
#define Ee 800000
#define Ff 128
#define Bb 64
#define EPSBN 1e-5f
#define DEGCAP 64
#define NTILES 391            // ceil(50000/128)

// ---------------- device scratch (zero-init; self-cleaning for graph replay) ----
__device__ __align__(16) float d_agg[Nn * Ff];   // mean-agg; layer2 GEMM writes pre2 here
__device__ __align__(16) float d_h[Nn * Ff];     // pre1 (pre-BN)
__device__ int   d_cnt_i[Nn];                    // degree; re-zeroed by layer-2 gather
__device__ int   d_esrc[Nn * DEGCAP];            // bucket adjacency
__device__ float d_sum[Ff];                      // re-zeroed by k_bnfin
__device__ float d_sqs[Ff];
__device__ __align__(16) float d_scale[Ff];
__device__ __align__(16) float d_shift[Ff];
__device__ __align__(16) float d_pool[Bb * Ff];  // re-zeroed by k_fin
__device__ float d_cnt[Bb];                      // re-zeroed by k_fin
// prepacked weight fragments (mma register order), tf32 hi/lo: [layer][32768]
__device__ __align__(16) float d_wfh[2][32768];
__device__ __align__(16) float d_wfl[2][32768];

// ---------------- helpers ----------------
__device__ __forceinline__ float tf32r(float x) {
    uint32_t u;
    asm("cvt.rna.tf32.f32 %0, %1;" : "=r"(u) : "f"(x));
    return __uint_as_float(u);
}
// D += A(16x8 tf32) * B(8x8 tf32), fp32 accumulate (Ampere-class HMMA, no 'a' gating)
__device__ __forceinline__ void mma1688(float* c, const uint4 a, const uint32_t b0, const uint32_t b1) {
    asm volatile("mma.sync.aligned.m16n8k8.row.col.f32.tf32.tf32.f32 "
        "{%0,%1,%2,%3}, {%4,%5,%6,%7}, {%8,%9}, {%0,%1,%2,%3};"
        : "+f"(c[0]), "+f"(c[1]), "+f"(c[2]), "+f"(c[3])
        : "r"(a.x), "r"(a.y), "r"(a.z), "r"(a.w), "r"(b0), "r"(b1));
}

// ---------------- bucket adjacency build ----------------
__global__ void k_fillb(const int* __restrict__ src, const int* __restrict__ dst) {
    int e = blockIdx.x * blockDim.x + threadIdx.x;
    if (e < Ee) {
        int d = dst[e];
        int pos = atomicAdd(&d_cnt_i[d], 1);
        if (pos < DEGCAP) d_esrc[d * DEGCAP + pos] = src[e];
    }
}

// ---------------- weight prepack: B fragments in mma register order --------------
// B frag for mma.m16n8k8 col: b0 = W[f = n8*8 + lane/4][k = K8*8 + lane%4],
//                             b1 = same f, k+4.
// Packed as [K8(32)][p(8)][lane(32)][4] with j = {n8a b0, n8a b1, n8b b0, n8b b1},
// n8a = 2p, n8b = 2p+1. Stacked K: k<128 -> Wl, else Wr. tf32 hi/lo split.
__global__ void k_wprep(const float* __restrict__ wl1, const float* __restrict__ wr1,
                        const float* __restrict__ wl2, const float* __restrict__ wr2) {
    int idx = blockIdx.x * blockDim.x + threadIdx.x;   // 0..65535
    if (idx >= 65536) return;
    int layer = idx >> 15;
    int rem = idx & 32767;
    int pos = rem >> 2;                 // (K8, p, lane)
    int j = rem & 3;
    int K8 = pos >> 8;
    int p = (pos >> 5) & 7;
    int lane = pos & 31;
    int n8 = 2 * p + (j >> 1);
    int f = n8 * 8 + (lane >> 2);
    int k = K8 * 8 + (lane & 3) + (j & 1) * 4;
    const float* wl = layer ? wl2 : wl1;
    const float* wr = layer ? wr2 : wr1;
    float w = (k < 128) ? wl[k * 128 + f] : wr[(k - 128) * 128 + f];
    float hi = tf32r(w);
    float lo = tf32r(w - hi);
    d_wfh[layer][rem] = hi;
    d_wfl[layer][rem] = lo;
}

// ---------------- pull gather: warp per node, mean aggregation ------------------
__global__ void k_gather(const float* __restrict__ xin, int useH, int norm, int clearCnt) {
    int n = (blockIdx.x * blockDim.x + threadIdx.x) >> 5;
    int lane = threadIdx.x & 31;
    if (n >= Nn) return;
    const float* feat = useH ? (const float*)d_h : xin;
    const float4* f4 = reinterpret_cast<const float4*>(feat);
    const int deg = d_cnt_i[n];
    const int m = deg < DEGCAP ? deg : DEGCAP;
    const int* eb = d_esrc + n * DEGCAP;
    float4 acc = make_float4(0.f, 0.f, 0.f, 0.f);
    float4 sc, sh;
    if (norm) {
        sc = reinterpret_cast<const float4*>(d_scale)[lane];
        sh = reinterpret_cast<const float4*>(d_shift)[lane];
    }
#define NORM4(v) if (norm) { \
        v.x = fmaxf(fmaf(v.x, sc.x, sh.x), 0.f); v.y = fmaxf(fmaf(v.y, sc.y, sh.y), 0.f); \
        v.z = fmaxf(fmaf(v.z, sc.z, sh.z), 0.f); v.w = fmaxf(fmaf(v.w, sc.w, sh.w), 0.f); }
    int j = 0;
    for (; j + 8 <= m; j += 8) {
        int e0 = eb[j],     e1 = eb[j + 1], e2 = eb[j + 2], e3 = eb[j + 3];
        int e4 = eb[j + 4], e5 = eb[j + 5], e6 = eb[j + 6], e7 = eb[j + 7];
        float4 v0 = f4[e0 * 32 + lane];
        float4 v1 = f4[e1 * 32 + lane];
        float4 v2 = f4[e2 * 32 + lane];
        float4 v3 = f4[e3 * 32 + lane];
        float4 v4 = f4[e4 * 32 + lane];
        float4 v5 = f4[e5 * 32 + lane];
        float4 v6 = f4[e6 * 32 + lane];
        float4 v7 = f4[e7 * 32 + lane];
        NORM4(v0) NORM4(v1) NORM4(v2) NORM4(v3)
        NORM4(v4) NORM4(v5) NORM4(v6) NORM4(v7)
        acc.x += (v0.x + v1.x) + (v2.x + v3.x) + (v4.x + v5.x) + (v6.x + v7.x);
        acc.y += (v0.y + v1.y) + (v2.y + v3.y) + (v4.y + v5.y) + (v6.y + v7.y);
        acc.z += (v0.z + v1.z) + (v2.z + v3.z) + (v4.z + v5.z) + (v6.z + v7.z);
        acc.w += (v0.w + v1.w) + (v2.w + v3.w) + (v4.w + v5.w) + (v6.w + v7.w);
    }
    for (; j < m; j++) {
        int e0 = eb[j];
        float4 v0 = f4[e0 * 32 + lane];
        NORM4(v0)
        acc.x += v0.x; acc.y += v0.y; acc.z += v0.z; acc.w += v0.w;
    }
#undef NORM4
    float inv = 1.f / fmaxf((float)deg, 1.f);
    acc.x *= inv; acc.y *= inv; acc.z *= inv; acc.w *= inv;
    reinterpret_cast<float4*>(d_agg)[n * 32 + lane] = acc;
    if (clearCnt && lane == 0) d_cnt_i[n] = 0;
}

// ---------------- tensor-core dual GEMM (mma.sync tf32, 3x split) ----------------
// D[128n x 128f] = A[128n x 256k] * B^T + bias.  A = [agg | BNrelu(self)].
// 8 warps: warp w = m16 block w (16 nodes), all 128 feats (16 n8 tiles).
// K staged in 4 chunks of 64; A gathered straight into fragment order (hi/lo).
// smem float offsets
#define SM_BIAS  0
#define SM_SCALE 128
#define SM_SHIFT 256
#define SM_AH    384
#define SM_AL    (384 + 8192)
#define SM_BH    (384 + 16384)
#define SM_BL    (384 + 24576)
#define SMEM_TFL (384 + 32768)
#define SMEM_TB  (SMEM_TFL * 4)

__global__ void __launch_bounds__(256, 1)
k_gemmT(const float* __restrict__ xin, const float* __restrict__ bias, int layer) {
    extern __shared__ float sm[];
    uint4* sAh = reinterpret_cast<uint4*>(sm + SM_AH);
    uint4* sAl = reinterpret_cast<uint4*>(sm + SM_AL);
    uint4* sBh = reinterpret_cast<uint4*>(sm + SM_BH);
    uint4* sBl = reinterpret_cast<uint4*>(sm + SM_BL);

    const int tid = threadIdx.x;
    const int lane = tid & 31;
    const int w = tid >> 5;           // warp = m16 block
    const int g = lane >> 2;          // groupID
    const int tig = lane & 3;

    const float* aggp  = (const float*)d_agg;
    const float* selfp = (layer == 1) ? xin : (const float*)d_h;
    float* outp = (layer == 1) ? (float*)d_h : (float*)d_agg;
    const float* gbh = d_wfh[layer - 1];
    const float* gbl = d_wfl[layer - 1];

    if (tid < 128) {
        sm[SM_BIAS + tid]  = bias[tid];
        sm[SM_SCALE + tid] = d_scale[tid];
        sm[SM_SHIFT + tid] = d_shift[tid];
    }
    __syncthreads();

    for (int t = blockIdx.x; t < NTILES; t += gridDim.x) {
        const int base = t * 128;

        // init accumulators with bias
        float acc[16][4];
#pragma unroll
        for (int n8 = 0; n8 < 16; n8++) {
            float b0 = sm[SM_BIAS + n8 * 8 + 2 * tig];
            float b1 = sm[SM_BIAS + n8 * 8 + 2 * tig + 1];
            acc[n8][0] = b0; acc[n8][1] = b1;
            acc[n8][2] = b0; acc[n8][3] = b1;
        }

        for (int c = 0; c < 4; c++) {
            __syncthreads();   // smem free (prev phase consumed)
            // ---- stage A fragments (hi/lo): positions (k8, m16, lane_) ----
            for (int i = tid; i < 2048; i += 256) {
                int lp  = i & 31;
                int m16 = (i >> 5) & 7;
                int k8  = i >> 8;
                int n0 = base + m16 * 16 + (lp >> 2);
                int kg = c * 64 + k8 * 8 + (lp & 3);
                float v[4];  // a0=(n0,kg) a1=(n0+8,kg) a2=(n0,kg+4) a3=(n0+8,kg+4)
#pragma unroll
                for (int q = 0; q < 4; q++) {
                    int nn = n0 + (q & 1) * 8;
                    int kk = kg + (q >> 1) * 4;
                    float val = 0.f;
                    if (nn < Nn) {
                        if (kk < 128) {
                            val = aggp[nn * 128 + kk];
                        } else {
                            val = selfp[nn * 128 + kk - 128];
                            if (layer == 2) {
                                val = fmaxf(fmaf(val, sm[SM_SCALE + kk - 128],
                                                 sm[SM_SHIFT + kk - 128]), 0.f);
                            }
                        }
                    }
                    v[q] = val;
                }
                float h0 = tf32r(v[0]), h1 = tf32r(v[1]), h2 = tf32r(v[2]), h3 = tf32r(v[3]);
                float l0 = tf32r(v[0] - h0), l1 = tf32r(v[1] - h1);
                float l2 = tf32r(v[2] - h2), l3 = tf32r(v[3] - h3);
                sAh[i] = make_uint4(__float_as_uint(h0), __float_as_uint(h1),
                                    __float_as_uint(h2), __float_as_uint(h3));
                sAl[i] = make_uint4(__float_as_uint(l0), __float_as_uint(l1),
                                    __float_as_uint(l2), __float_as_uint(l3));
            }
            // ---- stage B fragments: raw copy (8192 floats each, this chunk) ----
            {
                const float4* gh4 = reinterpret_cast<const float4*>(gbh + c * 8192);
                const float4* gl4 = reinterpret_cast<const float4*>(gbl + c * 8192);
                for (int i = tid; i < 2048; i += 256) {
                    float4 a = gh4[i], b = gl4[i];
                    sBh[i] = make_uint4(__float_as_uint(a.x), __float_as_uint(a.y),
                                        __float_as_uint(a.z), __float_as_uint(a.w));
                    sBl[i] = make_uint4(__float_as_uint(b.x), __float_as_uint(b.y),
                                        __float_as_uint(b.z), __float_as_uint(b.w));
                }
            }
            __syncthreads();

            // ---- mma: 8 k8 steps ----
#pragma unroll 2
            for (int k8 = 0; k8 < 8; k8++) {
                uint4 ah = sAh[(k8 * 8 + w) * 32 + lane];
                uint4 al = sAl[(k8 * 8 + w) * 32 + lane];
#pragma unroll
                for (int p = 0; p < 8; p++) {
                    uint4 bh = sBh[(k8 * 8 + p) * 32 + lane];
                    uint4 bl = sBl[(k8 * 8 + p) * 32 + lane];
                    // n8a = 2p (regs .x,.y), n8b = 2p+1 (regs .z,.w)
                    mma1688(acc[2 * p],     ah, bl.x, bl.y);
                    mma1688(acc[2 * p],     al, bh.x, bh.y);
                    mma1688(acc[2 * p],     ah, bh.x, bh.y);
                    mma1688(acc[2 * p + 1], ah, bl.z, bl.w);
                    mma1688(acc[2 * p + 1], al, bh.z, bh.w);
                    mma1688(acc[2 * p + 1], ah, bh.z, bh.w);
                }
            }
        }

        // ---- epilogue: write D ----
        int row0 = base + w * 16 + g;
        int row1 = row0 + 8;
#pragma unroll
        for (int n8 = 0; n8 < 16; n8++) {
            int f0 = n8 * 8 + 2 * tig;
            if (row0 < Nn)
                *reinterpret_cast<float2*>(&outp[row0 * 128 + f0]) =
                    make_float2(acc[n8][0], acc[n8][1]);
            if (row1 < Nn)
                *reinterpret_cast<float2*>(&outp[row1 * 128 + f0]) =
                    make_float2(acc[n8][2], acc[n8][3]);
        }
    }
}

// ---------------- BN stats over pre-activations ----------------------------------
__global__ void k_bnstat(int layer) {
    const float* src = (layer == 1) ? (const float*)d_h : (const float*)d_agg;
    __shared__ float s1[128], s2[128];
    int tid = threadIdx.x;                 // 256
    if (tid < 128) { s1[tid] = 0.f; s2[tid] = 0.f; }
    __syncthreads();
    int f = tid & 127, h = tid >> 7;
    float a = 0.f, b = 0.f;
    for (int n = blockIdx.x * 2 + h; n < Nn; n += gridDim.x * 2) {
        float v = src[n * 128 + f];
        a += v; b += v * v;
    }
    atomicAdd(&s1[f], a);
    atomicAdd(&s2[f], b);
    __syncthreads();
    if (tid < 128) {
        atomicAdd(&d_sum[tid], s1[tid]);
        atomicAdd(&d_sqs[tid], s2[tid]);
    }
}

// ---------------- BN finalize (resets stats for next layer / replay) -------------
__global__ void k_bnfin(const float* __restrict__ g, const float* __restrict__ beta) {
    int fidx = threadIdx.x;
    float mu = d_sum[fidx] * (1.0f / Nn);
    float var = d_sqs[fidx] * (1.0f / Nn) - mu * mu;
    float sc = g[fidx] * rsqrtf(var + EPSBN);
    d_scale[fidx] = sc;
    d_shift[fidx] = beta[fidx] - mu * sc;
    d_sum[fidx] = 0.f;
    d_sqs[fidx] = 0.f;
}

// ---------------- fused norm+relu+pool: warp per node ----------------------------
__global__ void k_pool(const int* __restrict__ batch) {
    int n = (blockIdx.x * blockDim.x + threadIdx.x) >> 5;
    int lane = threadIdx.x & 31;
    if (n >= Nn) return;
    int b = batch[n];
    float4 v = reinterpret_cast<const float4*>(d_agg)[n * 32 + lane];
    float4 sc = reinterpret_cast<const float4*>(d_scale)[lane];
    float4 sh = reinterpret_cast<const float4*>(d_shift)[lane];
    v.x = fmaxf(fmaf(v.x, sc.x, sh.x), 0.f);
    v.y = fmaxf(fmaf(v.y, sc.y, sh.y), 0.f);
    v.z = fmaxf(fmaf(v.z, sc.z, sh.z), 0.f);
    v.w = fmaxf(fmaf(v.w, sc.w, sh.w), 0.f);
    float* pp = d_pool + b * 128 + lane * 4;
    asm volatile("red.global.add.v4.f32 [%0], {%1,%2,%3,%4};"
                 :: "l"(pp), "f"(v.x), "f"(v.y), "f"(v.z), "f"(v.w) : "memory");
    if (lane == 0) atomicAdd(d_cnt + b, 1.0f);
}

// ---------------- finalize (single block; self-cleans d_pool/d_cnt) --------------
__global__ void k_fin(float* __restrict__ out) {
    int tid = threadIdx.x;
    for (int i = tid; i < Bb * Ff; i += 1024) {
        float c = d_cnt[i >> 7];
        out[i] = d_pool[i] / fmaxf(c, 1.f);
    }
    __syncthreads();
    for (int i = tid; i < Bb * Ff; i += 1024) d_pool[i] = 0.f;
    if (tid < Bb) d_cnt[tid] = 0.f;
}

// ---------------- launcher --------------------------------------------------------
extern "C" void kernel_launch(void* const* d_in, const int* in_sizes, int n_in,
                              void* d_out, int out_size) {
    const float* x     = (const float*)d_in[0];
    const int*   ei    = (const int*)d_in[1];
    const int*   batch = (const int*)d_in[2];
    const float* wl1   = (const float*)d_in[3];
    const float* bl1   = (const float*)d_in[4];
    const float* wr1   = (const float*)d_in[5];
    const float* g1    = (const float*)d_in[6];
    const float* beta1 = (const float*)d_in[7];
    const float* wl2   = (const float*)d_in[8];
    const float* bl2   = (const float*)d_in[9];
    const float* wr2   = (const float*)d_in[10];
    const float* g2    = (const float*)d_in[11];
    const float* beta2 = (const float*)d_in[12];
    const int* src = ei;
    const int* dst = ei + Ee;
    float* out = (float*)d_out;

    cudaFuncSetAttribute(k_gemmT, cudaFuncAttributeMaxDynamicSharedMemorySize, SMEM_TB);

    const int edgeBlocks = (Ee + 255) / 256;
    const int gatherBlocks = (Nn * 32 + 255) / 256;

    k_fillb<<<edgeBlocks, 256>>>(src, dst);                    // 0
    k_wprep<<<256, 256>>>(wl1, wr1, wl2, wr2);                 // 1

    // ---- layer 1 ----
    k_gather<<<gatherBlocks, 256>>>(x, 0, 0, 0);               // 2
    k_gemmT<<<148, 256, SMEM_TB>>>(x, bl1, 1);                 // 3  <- profiled
    k_bnstat<<<148, 256>>>(1);                                 // 4
    k_bnfin<<<1, 128>>>(g1, beta1);                            // 5

    // ---- layer 2 ----
    k_gather<<<gatherBlocks, 256>>>(x, 1, 1, 1);               // 6
    k_gemmT<<<148, 256, SMEM_TB>>>(x, bl2, 2);                 // 7
    k_bnstat<<<148, 256>>>(2);                                 // 8
    k_bnfin<<<1, 128>>>(g2, beta2);                            // 9

    // ---- pool ----
    k_pool<<<(Nn + 7) / 8, 256>>>(batch);                      // 10
    k_fin<<<1, 1024>>>(out);                                   // 11
}

// round 12
// speedup vs baseline: 1.0601x; 1.0601x over previous
#include <cuda_runtime.h>
#include <cstdint>

#define Nn 50000
#define Ee 800000
#define Ff 128
#define Bb 64
#define EPSBN 1e-5f
#define DEGCAP 64
#define NT64 782              // ceil(50000/64)

// ---------------- device scratch (zero-init; self-cleaning for graph replay) ----
__device__ __align__(16) float d_agg[Nn * Ff];   // mean-agg; layer2 GEMM writes pre2 here
__device__ __align__(16) float d_h[Nn * Ff];     // pre1 (pre-BN)
__device__ int   d_cnt_i[Nn];                    // degree; re-zeroed by layer-2 gather
__device__ int   d_esrc[Nn * DEGCAP];            // bucket adjacency
__device__ float d_sum[Ff];                      // re-zeroed by k_bnfin
__device__ float d_sqs[Ff];
__device__ __align__(16) float d_scale[Ff];
__device__ __align__(16) float d_shift[Ff];
__device__ __align__(16) float d_pool[Bb * Ff];  // re-zeroed by k_fin
__device__ float d_cnt[Bb];                      // re-zeroed by k_fin
// prepacked weight fragments (mma register order), tf32 hi/lo: [layer][32768]
__device__ __align__(16) float d_wfh[2][32768];
__device__ __align__(16) float d_wfl[2][32768];

// ---------------- helpers ----------------
__device__ __forceinline__ float tf32r(float x) {
    uint32_t u;
    asm("cvt.rna.tf32.f32 %0, %1;" : "=r"(u) : "f"(x));
    return __uint_as_float(u);
}
// D += A(16x8 tf32) * B(8x8 tf32), fp32 accumulate (Ampere-class HMMA, no 'a' gating)
__device__ __forceinline__ void mma1688(float* c, const uint4 a, const uint32_t b0, const uint32_t b1) {
    asm volatile("mma.sync.aligned.m16n8k8.row.col.f32.tf32.tf32.f32 "
        "{%0,%1,%2,%3}, {%4,%5,%6,%7}, {%8,%9}, {%0,%1,%2,%3};"
        : "+f"(c[0]), "+f"(c[1]), "+f"(c[2]), "+f"(c[3])
        : "r"(a.x), "r"(a.y), "r"(a.z), "r"(a.w), "r"(b0), "r"(b1));
}

// ---------------- bucket adjacency build ----------------
__global__ void k_fillb(const int* __restrict__ src, const int* __restrict__ dst) {
    int e = blockIdx.x * blockDim.x + threadIdx.x;
    if (e < Ee) {
        int d = dst[e];
        int pos = atomicAdd(&d_cnt_i[d], 1);
        if (pos < DEGCAP) d_esrc[d * DEGCAP + pos] = src[e];
    }
}

// ---------------- weight prepack: B fragments in mma register order --------------
// Packed as [K8(32)][p(8)][lane(32)][4]; j = {n8a b0, n8a b1, n8b b0, n8b b1},
// n8a = 2p, n8b = 2p+1. Stacked K: k<128 -> Wl, else Wr. tf32 hi/lo split.
__global__ void k_wprep(const float* __restrict__ wl1, const float* __restrict__ wr1,
                        const float* __restrict__ wl2, const float* __restrict__ wr2) {
    int idx = blockIdx.x * blockDim.x + threadIdx.x;   // 0..65535
    if (idx >= 65536) return;
    int layer = idx >> 15;
    int rem = idx & 32767;
    int pos = rem >> 2;                 // (K8, p, lane)
    int j = rem & 3;
    int K8 = pos >> 8;
    int p = (pos >> 5) & 7;
    int lane = pos & 31;
    int n8 = 2 * p + (j >> 1);
    int f = n8 * 8 + (lane >> 2);
    int k = K8 * 8 + (lane & 3) + (j & 1) * 4;
    const float* wl = layer ? wl2 : wl1;
    const float* wr = layer ? wr2 : wr1;
    float w = (k < 128) ? wl[k * 128 + f] : wr[(k - 128) * 128 + f];
    float hi = tf32r(w);
    float lo = tf32r(w - hi);
    d_wfh[layer][rem] = hi;
    d_wfl[layer][rem] = lo;
}

// ---------------- pull gather: warp per node, mean aggregation ------------------
__global__ void k_gather(const float* __restrict__ xin, int useH, int norm, int clearCnt) {
    int n = (blockIdx.x * blockDim.x + threadIdx.x) >> 5;
    int lane = threadIdx.x & 31;
    if (n >= Nn) return;
    const float* feat = useH ? (const float*)d_h : xin;
    const float4* f4 = reinterpret_cast<const float4*>(feat);
    const int deg = d_cnt_i[n];
    const int m = deg < DEGCAP ? deg : DEGCAP;
    const int* eb = d_esrc + n * DEGCAP;
    float4 acc = make_float4(0.f, 0.f, 0.f, 0.f);
    float4 sc, sh;
    if (norm) {
        sc = reinterpret_cast<const float4*>(d_scale)[lane];
        sh = reinterpret_cast<const float4*>(d_shift)[lane];
    }
#define NORM4(v) if (norm) { \
        v.x = fmaxf(fmaf(v.x, sc.x, sh.x), 0.f); v.y = fmaxf(fmaf(v.y, sc.y, sh.y), 0.f); \
        v.z = fmaxf(fmaf(v.z, sc.z, sh.z), 0.f); v.w = fmaxf(fmaf(v.w, sc.w, sh.w), 0.f); }
    int j = 0;
    for (; j + 8 <= m; j += 8) {
        int e0 = eb[j],     e1 = eb[j + 1], e2 = eb[j + 2], e3 = eb[j + 3];
        int e4 = eb[j + 4], e5 = eb[j + 5], e6 = eb[j + 6], e7 = eb[j + 7];
        float4 v0 = f4[e0 * 32 + lane];
        float4 v1 = f4[e1 * 32 + lane];
        float4 v2 = f4[e2 * 32 + lane];
        float4 v3 = f4[e3 * 32 + lane];
        float4 v4 = f4[e4 * 32 + lane];
        float4 v5 = f4[e5 * 32 + lane];
        float4 v6 = f4[e6 * 32 + lane];
        float4 v7 = f4[e7 * 32 + lane];
        NORM4(v0) NORM4(v1) NORM4(v2) NORM4(v3)
        NORM4(v4) NORM4(v5) NORM4(v6) NORM4(v7)
        acc.x += (v0.x + v1.x) + (v2.x + v3.x) + (v4.x + v5.x) + (v6.x + v7.x);
        acc.y += (v0.y + v1.y) + (v2.y + v3.y) + (v4.y + v5.y) + (v6.y + v7.y);
        acc.z += (v0.z + v1.z) + (v2.z + v3.z) + (v4.z + v5.z) + (v6.z + v7.z);
        acc.w += (v0.w + v1.w) + (v2.w + v3.w) + (v4.w + v5.w) + (v6.w + v7.w);
    }
    for (; j < m; j++) {
        int e0 = eb[j];
        float4 v0 = f4[e0 * 32 + lane];
        NORM4(v0)
        acc.x += v0.x; acc.y += v0.y; acc.z += v0.z; acc.w += v0.w;
    }
#undef NORM4
    float inv = 1.f / fmaxf((float)deg, 1.f);
    acc.x *= inv; acc.y *= inv; acc.z *= inv; acc.w *= inv;
    reinterpret_cast<float4*>(d_agg)[n * 32 + lane] = acc;
    if (clearCnt && lane == 0) d_cnt_i[n] = 0;
}

// ---------------- tensor-core dual GEMM (mma.sync tf32, 3x split) ----------------
// CTA tile = 64 nodes x 128 feats; ~98KB smem -> 2 CTAs/SM for staging/mma overlap.
// 8 warps: m16 = w&3 (16-node block), fh = w>>2 (feature half, 8 n8 tiles).
// K stacked 256 = [agg | BNrelu(self)], staged in 4 chunks of 64.
// smem float offsets
#define SM_BIAS  0
#define SM_SCALE 128
#define SM_SHIFT 256
#define SM_AH    384
#define SM_AL    (384 + 4096)
#define SM_BH    (384 + 8192)
#define SM_BL    (384 + 16384)
#define SMEM_TFL (384 + 24576)
#define SMEM_TB  (SMEM_TFL * 4)

__global__ void __launch_bounds__(256, 2)
k_gemmT(const float* __restrict__ xin, const float* __restrict__ bias, int layer) {
    extern __shared__ float sm[];
    uint4* sAh = reinterpret_cast<uint4*>(sm + SM_AH);
    uint4* sAl = reinterpret_cast<uint4*>(sm + SM_AL);
    uint4* sBh = reinterpret_cast<uint4*>(sm + SM_BH);
    uint4* sBl = reinterpret_cast<uint4*>(sm + SM_BL);

    const int tid = threadIdx.x;
    const int lane = tid & 31;
    const int w = tid >> 5;
    const int m16 = w & 3;            // node 16-block within tile
    const int fh  = w >> 2;           // feature half
    const int g = lane >> 2;          // groupID
    const int tig = lane & 3;

    const float* aggp  = (const float*)d_agg;
    const float* selfp = (layer == 1) ? xin : (const float*)d_h;
    float* outp = (layer == 1) ? (float*)d_h : (float*)d_agg;
    const float* gbh = d_wfh[layer - 1];
    const float* gbl = d_wfl[layer - 1];

    if (tid < 128) {
        sm[SM_BIAS + tid]  = bias[tid];
        sm[SM_SCALE + tid] = d_scale[tid];
        sm[SM_SHIFT + tid] = d_shift[tid];
    }
    __syncthreads();

    for (int t = blockIdx.x; t < NT64; t += gridDim.x) {
        const int base = t * 64;

        // init accumulators with bias (a = local n8, global n8 = fh*8 + a)
        float acc[8][4];
#pragma unroll
        for (int a = 0; a < 8; a++) {
            int f0 = fh * 64 + a * 8 + 2 * tig;
            float b0 = sm[SM_BIAS + f0];
            float b1 = sm[SM_BIAS + f0 + 1];
            acc[a][0] = b0; acc[a][1] = b1;
            acc[a][2] = b0; acc[a][3] = b1;
        }

        for (int c = 0; c < 4; c++) {
            __syncthreads();   // smem free (prev chunk consumed)
            // ---- stage A fragments (hi/lo): 1024 slots (k8[8], m16[4], lane[32]) ----
            for (int i = tid; i < 1024; i += 256) {
                int lp  = i & 31;
                int mm  = (i >> 5) & 3;
                int k8  = i >> 7;
                int n0 = base + mm * 16 + (lp >> 2);
                int kg = c * 64 + k8 * 8 + (lp & 3);
                float v[4];  // (n0,kg) (n0+8,kg) (n0,kg+4) (n0+8,kg+4)
#pragma unroll
                for (int q = 0; q < 4; q++) {
                    int nn = n0 + (q & 1) * 8;
                    int kk = kg + (q >> 1) * 4;
                    float val = 0.f;
                    if (nn < Nn) {
                        if (kk < 128) {
                            val = aggp[nn * 128 + kk];
                        } else {
                            val = selfp[nn * 128 + kk - 128];
                            if (layer == 2) {
                                val = fmaxf(fmaf(val, sm[SM_SCALE + kk - 128],
                                                 sm[SM_SHIFT + kk - 128]), 0.f);
                            }
                        }
                    }
                    v[q] = val;
                }
                float h0 = tf32r(v[0]), h1 = tf32r(v[1]), h2 = tf32r(v[2]), h3 = tf32r(v[3]);
                float l0 = tf32r(v[0] - h0), l1 = tf32r(v[1] - h1);
                float l2 = tf32r(v[2] - h2), l3 = tf32r(v[3] - h3);
                sAh[i] = make_uint4(__float_as_uint(h0), __float_as_uint(h1),
                                    __float_as_uint(h2), __float_as_uint(h3));
                sAl[i] = make_uint4(__float_as_uint(l0), __float_as_uint(l1),
                                    __float_as_uint(l2), __float_as_uint(l3));
            }
            // ---- stage B fragments: raw copy of this chunk (8192 floats each) ----
            {
                const float4* gh4 = reinterpret_cast<const float4*>(gbh + c * 8192);
                const float4* gl4 = reinterpret_cast<const float4*>(gbl + c * 8192);
                for (int i = tid; i < 2048; i += 256) {
                    float4 a = gh4[i], b = gl4[i];
                    sBh[i] = make_uint4(__float_as_uint(a.x), __float_as_uint(a.y),
                                        __float_as_uint(a.z), __float_as_uint(a.w));
                    sBl[i] = make_uint4(__float_as_uint(b.x), __float_as_uint(b.y),
                                        __float_as_uint(b.z), __float_as_uint(b.w));
                }
            }
            __syncthreads();

            // ---- mma: 8 k8 steps; 3 precision terms in separate sweeps for ILP ----
#pragma unroll 2
            for (int k8 = 0; k8 < 8; k8++) {
                uint4 ah = sAh[(k8 * 4 + m16) * 32 + lane];
                uint4 al = sAl[(k8 * 4 + m16) * 32 + lane];
                uint4 bh[4], bl[4];
#pragma unroll
                for (int pl = 0; pl < 4; pl++) {
                    int p = fh * 4 + pl;
                    bh[pl] = sBh[(k8 * 8 + p) * 32 + lane];
                    bl[pl] = sBl[(k8 * 8 + p) * 32 + lane];
                }
#pragma unroll
                for (int pl = 0; pl < 4; pl++) {
                    mma1688(acc[2 * pl],     ah, bl[pl].x, bl[pl].y);
                    mma1688(acc[2 * pl + 1], ah, bl[pl].z, bl[pl].w);
                }
#pragma unroll
                for (int pl = 0; pl < 4; pl++) {
                    mma1688(acc[2 * pl],     al, bh[pl].x, bh[pl].y);
                    mma1688(acc[2 * pl + 1], al, bh[pl].z, bh[pl].w);
                }
#pragma unroll
                for (int pl = 0; pl < 4; pl++) {
                    mma1688(acc[2 * pl],     ah, bh[pl].x, bh[pl].y);
                    mma1688(acc[2 * pl + 1], ah, bh[pl].z, bh[pl].w);
                }
            }
        }

        // ---- epilogue: write D ----
        int row0 = base + m16 * 16 + g;
        int row1 = row0 + 8;
#pragma unroll
        for (int a = 0; a < 8; a++) {
            int f0 = fh * 64 + a * 8 + 2 * tig;
            if (row0 < Nn)
                *reinterpret_cast<float2*>(&outp[row0 * 128 + f0]) =
                    make_float2(acc[a][0], acc[a][1]);
            if (row1 < Nn)
                *reinterpret_cast<float2*>(&outp[row1 * 128 + f0]) =
                    make_float2(acc[a][2], acc[a][3]);
        }
    }
}

// ---------------- BN stats over pre-activations ----------------------------------
__global__ void k_bnstat(int layer) {
    const float* src = (layer == 1) ? (const float*)d_h : (const float*)d_agg;
    __shared__ float s1[128], s2[128];
    int tid = threadIdx.x;                 // 256
    if (tid < 128) { s1[tid] = 0.f; s2[tid] = 0.f; }
    __syncthreads();
    int f = tid & 127, h = tid >> 7;
    float a = 0.f, b = 0.f;
    for (int n = blockIdx.x * 2 + h; n < Nn; n += gridDim.x * 2) {
        float v = src[n * 128 + f];
        a += v; b += v * v;
    }
    atomicAdd(&s1[f], a);
    atomicAdd(&s2[f], b);
    __syncthreads();
    if (tid < 128) {
        atomicAdd(&d_sum[tid], s1[tid]);
        atomicAdd(&d_sqs[tid], s2[tid]);
    }
}

// ---------------- BN finalize (resets stats for next layer / replay) -------------
__global__ void k_bnfin(const float* __restrict__ g, const float* __restrict__ beta) {
    int fidx = threadIdx.x;
    float mu = d_sum[fidx] * (1.0f / Nn);
    float var = d_sqs[fidx] * (1.0f / Nn) - mu * mu;
    float sc = g[fidx] * rsqrtf(var + EPSBN);
    d_scale[fidx] = sc;
    d_shift[fidx] = beta[fidx] - mu * sc;
    d_sum[fidx] = 0.f;
    d_sqs[fidx] = 0.f;
}

// ---------------- fused norm+relu+pool: warp per node ----------------------------
__global__ void k_pool(const int* __restrict__ batch) {
    int n = (blockIdx.x * blockDim.x + threadIdx.x) >> 5;
    int lane = threadIdx.x & 31;
    if (n >= Nn) return;
    int b = batch[n];
    float4 v = reinterpret_cast<const float4*>(d_agg)[n * 32 + lane];
    float4 sc = reinterpret_cast<const float4*>(d_scale)[lane];
    float4 sh = reinterpret_cast<const float4*>(d_shift)[lane];
    v.x = fmaxf(fmaf(v.x, sc.x, sh.x), 0.f);
    v.y = fmaxf(fmaf(v.y, sc.y, sh.y), 0.f);
    v.z = fmaxf(fmaf(v.z, sc.z, sh.z), 0.f);
    v.w = fmaxf(fmaf(v.w, sc.w, sh.w), 0.f);
    float* pp = d_pool + b * 128 + lane * 4;
    asm volatile("red.global.add.v4.f32 [%0], {%1,%2,%3,%4};"
                 :: "l"(pp), "f"(v.x), "f"(v.y), "f"(v.z), "f"(v.w) : "memory");
    if (lane == 0) atomicAdd(d_cnt + b, 1.0f);
}

// ---------------- finalize (single block; self-cleans d_pool/d_cnt) --------------
__global__ void k_fin(float* __restrict__ out) {
    int tid = threadIdx.x;
    for (int i = tid; i < Bb * Ff; i += 1024) {
        float c = d_cnt[i >> 7];
        out[i] = d_pool[i] / fmaxf(c, 1.f);
    }
    __syncthreads();
    for (int i = tid; i < Bb * Ff; i += 1024) d_pool[i] = 0.f;
    if (tid < Bb) d_cnt[tid] = 0.f;
}

// ---------------- launcher --------------------------------------------------------
extern "C" void kernel_launch(void* const* d_in, const int* in_sizes, int n_in,
                              void* d_out, int out_size) {
    const float* x     = (const float*)d_in[0];
    const int*   ei    = (const int*)d_in[1];
    const int*   batch = (const int*)d_in[2];
    const float* wl1   = (const float*)d_in[3];
    const float* bl1   = (const float*)d_in[4];
    const float* wr1   = (const float*)d_in[5];
    const float* g1    = (const float*)d_in[6];
    const float* beta1 = (const float*)d_in[7];
    const float* wl2   = (const float*)d_in[8];
    const float* bl2   = (const float*)d_in[9];
    const float* wr2   = (const float*)d_in[10];
    const float* g2    = (const float*)d_in[11];
    const float* beta2 = (const float*)d_in[12];
    const int* src = ei;
    const int* dst = ei + Ee;
    float* out = (float*)d_out;

    cudaFuncSetAttribute(k_gemmT, cudaFuncAttributeMaxDynamicSharedMemorySize, SMEM_TB);

    const int edgeBlocks = (Ee + 255) / 256;
    const int gatherBlocks = (Nn * 32 + 255) / 256;

    k_fillb<<<edgeBlocks, 256>>>(src, dst);                    // 0
    k_wprep<<<256, 256>>>(wl1, wr1, wl2, wr2);                 // 1

    // ---- layer 1 ----
    k_gather<<<gatherBlocks, 256>>>(x, 0, 0, 0);               // 2
    k_gemmT<<<296, 256, SMEM_TB>>>(x, bl1, 1);                 // 3  <- profiled
    k_bnstat<<<148, 256>>>(1);                                 // 4
    k_bnfin<<<1, 128>>>(g1, beta1);                            // 5

    // ---- layer 2 ----
    k_gather<<<gatherBlocks, 256>>>(x, 1, 1, 1);               // 6
    k_gemmT<<<296, 256, SMEM_TB>>>(x, bl2, 2);                 // 7
    k_bnstat<<<148, 256>>>(2);                                 // 8
    k_bnfin<<<1, 128>>>(g2, beta2);                            // 9

    // ---- pool ----
    k_pool<<<(Nn + 7) / 8, 256>>>(batch);                      // 10
    k_fin<<<1, 1024>>>(out);                                   // 11
}

// round 13
// speedup vs baseline: 1.2408x; 1.1704x over previous
#include <cuda_runtime.h>
#include <cstdint>

#define Nn 50000
#define Ee 800000
#define Ff 128
#define Bb 64
#define EPSBN 1e-5f
#define DEGCAP 64
#define NT64 782              // ceil(50000/64)

// ---------------- device scratch (zero-init; self-cleaning for graph replay) ----
__device__ __align__(16) float d_agg[Nn * Ff];   // mean-agg; layer2 GEMM writes pre2 here
__device__ __align__(16) float d_h[Nn * Ff];     // pre1 (pre-BN)
__device__ int   d_cnt_i[Nn];                    // degree; re-zeroed by layer-2 gather
__device__ int   d_esrc[Nn * DEGCAP];            // bucket adjacency
__device__ float d_sum[Ff];                      // re-zeroed by k_bnfin
__device__ float d_sqs[Ff];
__device__ __align__(16) float d_scale[Ff];
__device__ __align__(16) float d_shift[Ff];
__device__ __align__(16) float d_pool[Bb * Ff];  // re-zeroed by k_fin
__device__ float d_cnt[Bb];                      // re-zeroed by k_fin
// prepacked weight fragments (mma register order), tf32 hi only: [layer][32768]
__device__ __align__(16) float d_wfh[2][32768];

// ---------------- helpers ----------------
__device__ __forceinline__ uint32_t smem_u32(const void* p) {
    uint32_t a;
    asm("{ .reg .u64 t; cvta.to.shared.u64 t, %1; cvt.u32.u64 %0, t; }" : "=r"(a) : "l"(p));
    return a;
}
__device__ __forceinline__ float tf32r(float x) {
    uint32_t u;
    asm("cvt.rna.tf32.f32 %0, %1;" : "=r"(u) : "f"(x));
    return __uint_as_float(u);
}
// D += A(16x8 tf32) * B(8x8 tf32), fp32 accumulate (Ampere-class HMMA)
__device__ __forceinline__ void mma1688(float* c, const uint4 a, const uint32_t b0, const uint32_t b1) {
    asm volatile("mma.sync.aligned.m16n8k8.row.col.f32.tf32.tf32.f32 "
        "{%0,%1,%2,%3}, {%4,%5,%6,%7}, {%8,%9}, {%0,%1,%2,%3};"
        : "+f"(c[0]), "+f"(c[1]), "+f"(c[2]), "+f"(c[3])
        : "r"(a.x), "r"(a.y), "r"(a.z), "r"(a.w), "r"(b0), "r"(b1));
}
#define CP_ASYNC16(sdst, gsrc) \
    asm volatile("cp.async.ca.shared.global [%0], [%1], 16;" :: "r"(sdst), "l"(gsrc) : "memory")
#define CP_COMMIT() asm volatile("cp.async.commit_group;" ::: "memory")
#define CP_WAIT0()  asm volatile("cp.async.wait_group 0;" ::: "memory")

// ---------------- bucket adjacency build ----------------
__global__ void k_fillb(const int* __restrict__ src, const int* __restrict__ dst) {
    int e = blockIdx.x * blockDim.x + threadIdx.x;
    if (e < Ee) {
        int d = dst[e];
        int pos = atomicAdd(&d_cnt_i[d], 1);
        if (pos < DEGCAP) d_esrc[d * DEGCAP + pos] = src[e];
    }
}

// ---------------- weight prepack: B fragments in mma register order (tf32 hi) ----
// Packed as [K8(32)][p(8)][lane(32)][4]; j = {n8a b0, n8a b1, n8b b0, n8b b1},
// n8a = 2p, n8b = 2p+1. Stacked K: k<128 -> Wl, else Wr.
__global__ void k_wprep(const float* __restrict__ wl1, const float* __restrict__ wr1,
                        const float* __restrict__ wl2, const float* __restrict__ wr2) {
    int idx = blockIdx.x * blockDim.x + threadIdx.x;   // 0..65535
    if (idx >= 65536) return;
    int layer = idx >> 15;
    int rem = idx & 32767;
    int pos = rem >> 2;                 // (K8, p, lane)
    int j = rem & 3;
    int K8 = pos >> 8;
    int p = (pos >> 5) & 7;
    int lane = pos & 31;
    int n8 = 2 * p + (j >> 1);
    int f = n8 * 8 + (lane >> 2);
    int k = K8 * 8 + (lane & 3) + (j & 1) * 4;
    const float* wl = layer ? wl2 : wl1;
    const float* wr = layer ? wr2 : wr1;
    float w = (k < 128) ? wl[k * 128 + f] : wr[(k - 128) * 128 + f];
    d_wfh[layer][rem] = tf32r(w);
}

// ---------------- pull gather: warp per node, mean aggregation ------------------
__global__ void k_gather(const float* __restrict__ xin, int useH, int norm, int clearCnt) {
    int n = (blockIdx.x * blockDim.x + threadIdx.x) >> 5;
    int lane = threadIdx.x & 31;
    if (n >= Nn) return;
    const float* feat = useH ? (const float*)d_h : xin;
    const float4* f4 = reinterpret_cast<const float4*>(feat);
    const int deg = d_cnt_i[n];
    const int m = deg < DEGCAP ? deg : DEGCAP;
    const int* eb = d_esrc + n * DEGCAP;
    float4 acc = make_float4(0.f, 0.f, 0.f, 0.f);
    float4 sc, sh;
    if (norm) {
        sc = reinterpret_cast<const float4*>(d_scale)[lane];
        sh = reinterpret_cast<const float4*>(d_shift)[lane];
    }
#define NORM4(v) if (norm) { \
        v.x = fmaxf(fmaf(v.x, sc.x, sh.x), 0.f); v.y = fmaxf(fmaf(v.y, sc.y, sh.y), 0.f); \
        v.z = fmaxf(fmaf(v.z, sc.z, sh.z), 0.f); v.w = fmaxf(fmaf(v.w, sc.w, sh.w), 0.f); }
    int j = 0;
    for (; j + 8 <= m; j += 8) {
        int e0 = eb[j],     e1 = eb[j + 1], e2 = eb[j + 2], e3 = eb[j + 3];
        int e4 = eb[j + 4], e5 = eb[j + 5], e6 = eb[j + 6], e7 = eb[j + 7];
        float4 v0 = f4[e0 * 32 + lane];
        float4 v1 = f4[e1 * 32 + lane];
        float4 v2 = f4[e2 * 32 + lane];
        float4 v3 = f4[e3 * 32 + lane];
        float4 v4 = f4[e4 * 32 + lane];
        float4 v5 = f4[e5 * 32 + lane];
        float4 v6 = f4[e6 * 32 + lane];
        float4 v7 = f4[e7 * 32 + lane];
        NORM4(v0) NORM4(v1) NORM4(v2) NORM4(v3)
        NORM4(v4) NORM4(v5) NORM4(v6) NORM4(v7)
        acc.x += (v0.x + v1.x) + (v2.x + v3.x) + (v4.x + v5.x) + (v6.x + v7.x);
        acc.y += (v0.y + v1.y) + (v2.y + v3.y) + (v4.y + v5.y) + (v6.y + v7.y);
        acc.z += (v0.z + v1.z) + (v2.z + v3.z) + (v4.z + v5.z) + (v6.z + v7.z);
        acc.w += (v0.w + v1.w) + (v2.w + v3.w) + (v4.w + v5.w) + (v6.w + v7.w);
    }
    for (; j < m; j++) {
        int e0 = eb[j];
        float4 v0 = f4[e0 * 32 + lane];
        NORM4(v0)
        acc.x += v0.x; acc.y += v0.y; acc.z += v0.z; acc.w += v0.w;
    }
#undef NORM4
    float inv = 1.f / fmaxf((float)deg, 1.f);
    acc.x *= inv; acc.y *= inv; acc.z *= inv; acc.w *= inv;
    reinterpret_cast<float4*>(d_agg)[n * 32 + lane] = acc;
    if (clearCnt && lane == 0) d_cnt_i[n] = 0;
}

// ---------------- tensor-core dual GEMM (mma.sync tf32, A split 2-term) ----------
// D = (Ah + Al) * Bh  (B rounded to tf32; error ~3e-4 << 1e-3 threshold).
// CTA tile = 64 nodes x 128 feats; smem ~66KB -> 3 CTAs/SM. One tile per CTA.
// 8 warps: m16 = w&3 (16-node block), fh = w>>2 (feature half).
// smem float offsets
#define SM_BIAS  0
#define SM_SCALE 128
#define SM_SHIFT 256
#define SM_AH    384
#define SM_AL    (384 + 4096)
#define SM_B     (384 + 8192)
#define SMEM_TFL (384 + 16384)
#define SMEM_TB  (SMEM_TFL * 4)

__global__ void __launch_bounds__(256, 3)
k_gemmT(const float* __restrict__ xin, const float* __restrict__ bias, int layer) {
    extern __shared__ float sm[];
    uint4* sAh = reinterpret_cast<uint4*>(sm + SM_AH);
    uint4* sAl = reinterpret_cast<uint4*>(sm + SM_AL);
    uint4* sB  = reinterpret_cast<uint4*>(sm + SM_B);

    const int tid = threadIdx.x;
    const int lane = tid & 31;
    const int w = tid >> 5;
    const int m16 = w & 3;            // node 16-block within tile
    const int fh  = w >> 2;           // feature half
    const int g = lane >> 2;          // groupID
    const int tig = lane & 3;

    const float* aggp  = (const float*)d_agg;
    const float* selfp = (layer == 1) ? xin : (const float*)d_h;
    float* outp = (layer == 1) ? (float*)d_h : (float*)d_agg;
    const float* gbh = d_wfh[layer - 1];

    if (tid < 128) {
        sm[SM_BIAS + tid]  = bias[tid];
        sm[SM_SCALE + tid] = d_scale[tid];
        sm[SM_SHIFT + tid] = d_shift[tid];
    }

    const int t = blockIdx.x;
    const int base = t * 64;

    // init accumulators with bias (a = local n8, global n8 = fh*8 + a)
    float acc[8][4];
    __syncthreads();
#pragma unroll
    for (int a = 0; a < 8; a++) {
        int f0 = fh * 64 + a * 8 + 2 * tig;
        float b0 = sm[SM_BIAS + f0];
        float b1 = sm[SM_BIAS + f0 + 1];
        acc[a][0] = b0; acc[a][1] = b1;
        acc[a][2] = b0; acc[a][3] = b1;
    }

    const uint32_t sBaddr = smem_u32(sB);

    for (int c = 0; c < 4; c++) {
        __syncthreads();   // smem free (prev chunk consumed)
        // ---- B fragments via cp.async (raw copy of this chunk, 8192 floats) ----
        {
            const float4* gh4 = reinterpret_cast<const float4*>(gbh + c * 8192);
            for (int i = tid; i < 2048; i += 256) {
                CP_ASYNC16(sBaddr + i * 16, (const void*)(gh4 + i));
            }
            CP_COMMIT();
        }
        // ---- stage A fragments (hi/lo): 1024 slots (k8[8], m16[4], lane[32]) ----
        for (int i = tid; i < 1024; i += 256) {
            int lp  = i & 31;
            int mm  = (i >> 5) & 3;
            int k8  = i >> 7;
            int n0 = base + mm * 16 + (lp >> 2);
            int kg = c * 64 + k8 * 8 + (lp & 3);
            float v[4];  // (n0,kg) (n0+8,kg) (n0,kg+4) (n0+8,kg+4)
#pragma unroll
            for (int q = 0; q < 4; q++) {
                int nn = n0 + (q & 1) * 8;
                int kk = kg + (q >> 1) * 4;
                float val = 0.f;
                if (nn < Nn) {
                    if (kk < 128) {
                        val = aggp[nn * 128 + kk];
                    } else {
                        val = selfp[nn * 128 + kk - 128];
                        if (layer == 2) {
                            val = fmaxf(fmaf(val, sm[SM_SCALE + kk - 128],
                                             sm[SM_SHIFT + kk - 128]), 0.f);
                        }
                    }
                }
                v[q] = val;
            }
            float h0 = tf32r(v[0]), h1 = tf32r(v[1]), h2 = tf32r(v[2]), h3 = tf32r(v[3]);
            float l0 = tf32r(v[0] - h0), l1 = tf32r(v[1] - h1);
            float l2 = tf32r(v[2] - h2), l3 = tf32r(v[3] - h3);
            sAh[i] = make_uint4(__float_as_uint(h0), __float_as_uint(h1),
                                __float_as_uint(h2), __float_as_uint(h3));
            sAl[i] = make_uint4(__float_as_uint(l0), __float_as_uint(l1),
                                __float_as_uint(l2), __float_as_uint(l3));
        }
        CP_WAIT0();
        __syncthreads();

        // ---- mma: 8 k8 steps; 2 precision sweeps (Al*Bh then Ah*Bh) ----
#pragma unroll 2
        for (int k8 = 0; k8 < 8; k8++) {
            uint4 ah = sAh[(k8 * 4 + m16) * 32 + lane];
            uint4 al = sAl[(k8 * 4 + m16) * 32 + lane];
            uint4 bh[4];
#pragma unroll
            for (int pl = 0; pl < 4; pl++) {
                int p = fh * 4 + pl;
                bh[pl] = sB[(k8 * 8 + p) * 32 + lane];
            }
#pragma unroll
            for (int pl = 0; pl < 4; pl++) {
                mma1688(acc[2 * pl],     al, bh[pl].x, bh[pl].y);
                mma1688(acc[2 * pl + 1], al, bh[pl].z, bh[pl].w);
            }
#pragma unroll
            for (int pl = 0; pl < 4; pl++) {
                mma1688(acc[2 * pl],     ah, bh[pl].x, bh[pl].y);
                mma1688(acc[2 * pl + 1], ah, bh[pl].z, bh[pl].w);
            }
        }
    }

    // ---- epilogue: write D ----
    int row0 = base + m16 * 16 + g;
    int row1 = row0 + 8;
#pragma unroll
    for (int a = 0; a < 8; a++) {
        int f0 = fh * 64 + a * 8 + 2 * tig;
        if (row0 < Nn)
            *reinterpret_cast<float2*>(&outp[row0 * 128 + f0]) =
                make_float2(acc[a][0], acc[a][1]);
        if (row1 < Nn)
            *reinterpret_cast<float2*>(&outp[row1 * 128 + f0]) =
                make_float2(acc[a][2], acc[a][3]);
    }
}

// ---------------- BN stats over pre-activations ----------------------------------
__global__ void k_bnstat(int layer) {
    const float* src = (layer == 1) ? (const float*)d_h : (const float*)d_agg;
    __shared__ float s1[128], s2[128];
    int tid = threadIdx.x;                 // 256
    if (tid < 128) { s1[tid] = 0.f; s2[tid] = 0.f; }
    __syncthreads();
    int f = tid & 127, h = tid >> 7;
    float a = 0.f, b = 0.f;
    for (int n = blockIdx.x * 2 + h; n < Nn; n += gridDim.x * 2) {
        float v = src[n * 128 + f];
        a += v; b += v * v;
    }
    atomicAdd(&s1[f], a);
    atomicAdd(&s2[f], b);
    __syncthreads();
    if (tid < 128) {
        atomicAdd(&d_sum[tid], s1[tid]);
        atomicAdd(&d_sqs[tid], s2[tid]);
    }
}

// ---------------- BN finalize (resets stats for next layer / replay) -------------
__global__ void k_bnfin(const float* __restrict__ g, const float* __restrict__ beta) {
    int fidx = threadIdx.x;
    float mu = d_sum[fidx] * (1.0f / Nn);
    float var = d_sqs[fidx] * (1.0f / Nn) - mu * mu;
    float sc = g[fidx] * rsqrtf(var + EPSBN);
    d_scale[fidx] = sc;
    d_shift[fidx] = beta[fidx] - mu * sc;
    d_sum[fidx] = 0.f;
    d_sqs[fidx] = 0.f;
}

// ---------------- fused norm+relu+pool: warp per node ----------------------------
__global__ void k_pool(const int* __restrict__ batch) {
    int n = (blockIdx.x * blockDim.x + threadIdx.x) >> 5;
    int lane = threadIdx.x & 31;
    if (n >= Nn) return;
    int b = batch[n];
    float4 v = reinterpret_cast<const float4*>(d_agg)[n * 32 + lane];
    float4 sc = reinterpret_cast<const float4*>(d_scale)[lane];
    float4 sh = reinterpret_cast<const float4*>(d_shift)[lane];
    v.x = fmaxf(fmaf(v.x, sc.x, sh.x), 0.f);
    v.y = fmaxf(fmaf(v.y, sc.y, sh.y), 0.f);
    v.z = fmaxf(fmaf(v.z, sc.z, sh.z), 0.f);
    v.w = fmaxf(fmaf(v.w, sc.w, sh.w), 0.f);
    float* pp = d_pool + b * 128 + lane * 4;
    asm volatile("red.global.add.v4.f32 [%0], {%1,%2,%3,%4};"
                 :: "l"(pp), "f"(v.x), "f"(v.y), "f"(v.z), "f"(v.w) : "memory");
    if (lane == 0) atomicAdd(d_cnt + b, 1.0f);
}

// ---------------- finalize (single block; self-cleans d_pool/d_cnt) --------------
__global__ void k_fin(float* __restrict__ out) {
    int tid = threadIdx.x;
    for (int i = tid; i < Bb * Ff; i += 1024) {
        float c = d_cnt[i >> 7];
        out[i] = d_pool[i] / fmaxf(c, 1.f);
    }
    __syncthreads();
    for (int i = tid; i < Bb * Ff; i += 1024) d_pool[i] = 0.f;
    if (tid < Bb) d_cnt[tid] = 0.f;
}

// ---------------- launcher --------------------------------------------------------
extern "C" void kernel_launch(void* const* d_in, const int* in_sizes, int n_in,
                              void* d_out, int out_size) {
    const float* x     = (const float*)d_in[0];
    const int*   ei    = (const int*)d_in[1];
    const int*   batch = (const int*)d_in[2];
    const float* wl1   = (const float*)d_in[3];
    const float* bl1   = (const float*)d_in[4];
    const float* wr1   = (const float*)d_in[5];
    const float* g1    = (const float*)d_in[6];
    const float* beta1 = (const float*)d_in[7];
    const float* wl2   = (const float*)d_in[8];
    const float* bl2   = (const float*)d_in[9];
    const float* wr2   = (const float*)d_in[10];
    const float* g2    = (const float*)d_in[11];
    const float* beta2 = (const float*)d_in[12];
    const int* src = ei;
    const int* dst = ei + Ee;
    float* out = (float*)d_out;

    cudaFuncSetAttribute(k_gemmT, cudaFuncAttributeMaxDynamicSharedMemorySize, SMEM_TB);

    const int edgeBlocks = (Ee + 255) / 256;
    const int gatherBlocks = (Nn * 32 + 255) / 256;

    k_fillb<<<edgeBlocks, 256>>>(src, dst);                    // 0
    k_wprep<<<256, 256>>>(wl1, wr1, wl2, wr2);                 // 1

    // ---- layer 1 ----
    k_gather<<<gatherBlocks, 256>>>(x, 0, 0, 0);               // 2
    k_gemmT<<<NT64, 256, SMEM_TB>>>(x, bl1, 1);                // 3  <- profiled
    k_bnstat<<<148, 256>>>(1);                                 // 4
    k_bnfin<<<1, 128>>>(g1, beta1);                            // 5

    // ---- layer 2 ----
    k_gather<<<gatherBlocks, 256>>>(x, 1, 1, 1);               // 6
    k_gemmT<<<NT64, 256, SMEM_TB>>>(x, bl2, 2);                // 7
    k_bnstat<<<148, 256>>>(2);                                 // 8
    k_bnfin<<<1, 128>>>(g2, beta2);                            // 9

    // ---- pool ----
    k_pool<<<(Nn + 7) / 8, 256>>>(batch);                      // 10
    k_fin<<<1, 1024>>>(out);                                   // 11
}

// round 14
// speedup vs baseline: 1.2791x; 1.0309x over previous
#include <cuda_runtime.h>
#include <cuda_fp16.h>
#include <cstdint>

#define Nn 50000
#define Ee 800000
#define Ff 128
#define Bb 64
#define EPSBN 1e-5f
#define DEGCAP 64
#define NT64 782              // ceil(50000/64)

// ---------------- device scratch (zero-init; self-cleaning for graph replay) ----
__device__ __align__(16) float d_agg[Nn * Ff];   // mean-agg; layer2 GEMM writes pre2 here
__device__ __align__(16) float d_h[Nn * Ff];     // pre1 fp32 (pre-BN)
__device__ __align__(16) __half d_xh[Nn * Ff];   // fp16 copy of x (gather input)
__device__ __align__(16) __half d_hh[Nn * Ff];   // fp16 copy of pre1 (gather-2 input)
__device__ int   d_cnt_i[Nn];                    // degree; re-zeroed by layer-2 gather
__device__ int   d_esrc[Nn * DEGCAP];            // bucket adjacency
__device__ float d_sum[Ff];                      // re-zeroed by k_bnfin
__device__ float d_sqs[Ff];
__device__ __align__(16) float d_scale[Ff];
__device__ __align__(16) float d_shift[Ff];
__device__ __align__(16) float d_pool[Bb * Ff];  // re-zeroed by k_fin
__device__ float d_cnt[Bb];                      // re-zeroed by k_fin
// prepacked weight fragments (mma register order), tf32 hi only: [layer][32768]
__device__ __align__(16) float d_wfh[2][32768];

// ---------------- helpers ----------------
__device__ __forceinline__ uint32_t smem_u32(const void* p) {
    uint32_t a;
    asm("{ .reg .u64 t; cvta.to.shared.u64 t, %1; cvt.u32.u64 %0, t; }" : "=r"(a) : "l"(p));
    return a;
}
__device__ __forceinline__ float tf32r(float x) {
    uint32_t u;
    asm("cvt.rna.tf32.f32 %0, %1;" : "=r"(u) : "f"(x));
    return __uint_as_float(u);
}
__device__ __forceinline__ void mma1688(float* c, const uint4 a, const uint32_t b0, const uint32_t b1) {
    asm volatile("mma.sync.aligned.m16n8k8.row.col.f32.tf32.tf32.f32 "
        "{%0,%1,%2,%3}, {%4,%5,%6,%7}, {%8,%9}, {%0,%1,%2,%3};"
        : "+f"(c[0]), "+f"(c[1]), "+f"(c[2]), "+f"(c[3])
        : "r"(a.x), "r"(a.y), "r"(a.z), "r"(a.w), "r"(b0), "r"(b1));
}
#define CP_ASYNC16(sdst, gsrc) \
    asm volatile("cp.async.ca.shared.global [%0], [%1], 16;" :: "r"(sdst), "l"(gsrc) : "memory")
#define CP_COMMIT() asm volatile("cp.async.commit_group;" ::: "memory")
#define CP_WAIT0()  asm volatile("cp.async.wait_group 0;" ::: "memory")

// ---------------- bucket adjacency build ----------------
__global__ void k_fillb(const int* __restrict__ src, const int* __restrict__ dst) {
    int e = blockIdx.x * blockDim.x + threadIdx.x;
    if (e < Ee) {
        int d = dst[e];
        int pos = atomicAdd(&d_cnt_i[d], 1);
        if (pos < DEGCAP) d_esrc[d * DEGCAP + pos] = src[e];
    }
}

// ---------------- prep: weight fragments (tf32 hi) + fp16 copy of x --------------
__global__ void k_prep(const float* __restrict__ x,
                       const float* __restrict__ wl1, const float* __restrict__ wr1,
                       const float* __restrict__ wl2, const float* __restrict__ wr2) {
    int gid = blockIdx.x * 256 + threadIdx.x;
    if (blockIdx.x < 256) {
        // weight fragments: [K8(32)][p(8)][lane(32)][4]
        int idx = gid;                  // 0..65535
        int layer = idx >> 15;
        int rem = idx & 32767;
        int pos = rem >> 2;
        int j = rem & 3;
        int K8 = pos >> 8;
        int p = (pos >> 5) & 7;
        int lane = pos & 31;
        int n8 = 2 * p + (j >> 1);
        int f = n8 * 8 + (lane >> 2);
        int k = K8 * 8 + (lane & 3) + (j & 1) * 4;
        const float* wl = layer ? wl2 : wl1;
        const float* wr = layer ? wr2 : wr1;
        float w = (k < 128) ? wl[k * 128 + f] : wr[(k - 128) * 128 + f];
        d_wfh[layer][rem] = tf32r(w);
    } else {
        int i = gid - 65536;            // float4 index into x
        if (i < Nn * 32) {
            float4 v = reinterpret_cast<const float4*>(x)[i];
            __half2* o = reinterpret_cast<__half2*>(d_xh) + 2 * i;
            o[0] = __floats2half2_rn(v.x, v.y);
            o[1] = __floats2half2_rn(v.z, v.w);
        }
    }
}

// ---------------- pull gather (fp16 inputs): warp per node, mean aggregation -----
__global__ void k_gather(int useH, int norm, int clearCnt) {
    int n = (blockIdx.x * blockDim.x + threadIdx.x) >> 5;
    int lane = threadIdx.x & 31;
    if (n >= Nn) return;
    const __half* feat = useH ? d_hh : d_xh;
    const uint2* f2 = reinterpret_cast<const uint2*>(feat);   // 32 uint2 per row
    const int deg = d_cnt_i[n];
    const int m = deg < DEGCAP ? deg : DEGCAP;
    const int* eb = d_esrc + n * DEGCAP;
    float4 acc = make_float4(0.f, 0.f, 0.f, 0.f);
    float4 sc, sh;
    if (norm) {
        sc = reinterpret_cast<const float4*>(d_scale)[lane];
        sh = reinterpret_cast<const float4*>(d_shift)[lane];
    }
#define CV4(u, v) { \
        __half2 _ha = *reinterpret_cast<__half2*>(&(u).x); \
        __half2 _hb = *reinterpret_cast<__half2*>(&(u).y); \
        float2 _pa = __half22float2(_ha); \
        float2 _pb = __half22float2(_hb); \
        v = make_float4(_pa.x, _pa.y, _pb.x, _pb.y); }
#define NORM4(v) if (norm) { \
        v.x = fmaxf(fmaf(v.x, sc.x, sh.x), 0.f); v.y = fmaxf(fmaf(v.y, sc.y, sh.y), 0.f); \
        v.z = fmaxf(fmaf(v.z, sc.z, sh.z), 0.f); v.w = fmaxf(fmaf(v.w, sc.w, sh.w), 0.f); }
    int j = 0;
    for (; j + 8 <= m; j += 8) {
        int e0 = eb[j],     e1 = eb[j + 1], e2 = eb[j + 2], e3 = eb[j + 3];
        int e4 = eb[j + 4], e5 = eb[j + 5], e6 = eb[j + 6], e7 = eb[j + 7];
        uint2 u0 = f2[e0 * 32 + lane];
        uint2 u1 = f2[e1 * 32 + lane];
        uint2 u2 = f2[e2 * 32 + lane];
        uint2 u3 = f2[e3 * 32 + lane];
        uint2 u4 = f2[e4 * 32 + lane];
        uint2 u5 = f2[e5 * 32 + lane];
        uint2 u6 = f2[e6 * 32 + lane];
        uint2 u7 = f2[e7 * 32 + lane];
        float4 v0, v1, v2, v3, v4, v5, v6, v7;
        CV4(u0, v0) CV4(u1, v1) CV4(u2, v2) CV4(u3, v3)
        CV4(u4, v4) CV4(u5, v5) CV4(u6, v6) CV4(u7, v7)
        NORM4(v0) NORM4(v1) NORM4(v2) NORM4(v3)
        NORM4(v4) NORM4(v5) NORM4(v6) NORM4(v7)
        acc.x += (v0.x + v1.x) + (v2.x + v3.x) + (v4.x + v5.x) + (v6.x + v7.x);
        acc.y += (v0.y + v1.y) + (v2.y + v3.y) + (v4.y + v5.y) + (v6.y + v7.y);
        acc.z += (v0.z + v1.z) + (v2.z + v3.z) + (v4.z + v5.z) + (v6.z + v7.z);
        acc.w += (v0.w + v1.w) + (v2.w + v3.w) + (v4.w + v5.w) + (v6.w + v7.w);
    }
    for (; j < m; j++) {
        uint2 u0 = f2[eb[j] * 32 + lane];
        float4 v0;
        CV4(u0, v0)
        NORM4(v0)
        acc.x += v0.x; acc.y += v0.y; acc.z += v0.z; acc.w += v0.w;
    }
#undef NORM4
#undef CV4
    float inv = 1.f / fmaxf((float)deg, 1.f);
    acc.x *= inv; acc.y *= inv; acc.z *= inv; acc.w *= inv;
    reinterpret_cast<float4*>(d_agg)[n * 32 + lane] = acc;
    if (clearCnt && lane == 0) d_cnt_i[n] = 0;
}

// ---------------- tensor-core dual GEMM (mma.sync tf32, in-register A split) -----
// D = (Ah + Al) * Bh. A staged raw fp32, split to tf32 hi/lo in registers at mma.
// CTA tile = 64 nodes x 128 feats; smem ~50KB -> 3 CTAs/SM. One tile per CTA.
// smem float offsets
#define SM_BIAS  0
#define SM_SCALE 128
#define SM_SHIFT 256
#define SM_A     384
#define SM_B     (384 + 4096)
#define SMEM_TFL (384 + 12288)
#define SMEM_TB  (SMEM_TFL * 4)

__global__ void __launch_bounds__(256, 3)
k_gemmT(const float* __restrict__ xin, const float* __restrict__ bias, int layer) {
    extern __shared__ float sm[];
    uint4* sA = reinterpret_cast<uint4*>(sm + SM_A);
    uint4* sB = reinterpret_cast<uint4*>(sm + SM_B);

    const int tid = threadIdx.x;
    const int lane = tid & 31;
    const int w = tid >> 5;
    const int m16 = w & 3;            // node 16-block within tile
    const int fh  = w >> 2;           // feature half
    const int g = lane >> 2;
    const int tig = lane & 3;

    const float* aggp  = (const float*)d_agg;
    const float* selfp = (layer == 1) ? xin : (const float*)d_h;
    float* outp = (layer == 1) ? (float*)d_h : (float*)d_agg;
    const float* gbh = d_wfh[layer - 1];

    if (tid < 128) {
        sm[SM_BIAS + tid]  = bias[tid];
        sm[SM_SCALE + tid] = d_scale[tid];
        sm[SM_SHIFT + tid] = d_shift[tid];
    }

    const int base = blockIdx.x * 64;

    float acc[8][4];
    __syncthreads();
#pragma unroll
    for (int a = 0; a < 8; a++) {
        int f0 = fh * 64 + a * 8 + 2 * tig;
        float b0 = sm[SM_BIAS + f0];
        float b1 = sm[SM_BIAS + f0 + 1];
        acc[a][0] = b0; acc[a][1] = b1;
        acc[a][2] = b0; acc[a][3] = b1;
    }

    const uint32_t sBaddr = smem_u32(sB);

    for (int c = 0; c < 4; c++) {
        __syncthreads();
        // ---- B fragments via cp.async (raw copy, 8192 floats) ----
        {
            const float4* gh4 = reinterpret_cast<const float4*>(gbh + c * 8192);
            for (int i = tid; i < 2048; i += 256) {
                CP_ASYNC16(sBaddr + i * 16, (const void*)(gh4 + i));
            }
            CP_COMMIT();
        }
        // ---- stage A raw fp32 fragments: 1024 slots (k8[8], m16[4], lane[32]) ----
        for (int i = tid; i < 1024; i += 256) {
            int lp  = i & 31;
            int mm  = (i >> 5) & 3;
            int k8  = i >> 7;
            int n0 = base + mm * 16 + (lp >> 2);
            int kg = c * 64 + k8 * 8 + (lp & 3);
            float v[4];
#pragma unroll
            for (int q = 0; q < 4; q++) {
                int nn = n0 + (q & 1) * 8;
                int kk = kg + (q >> 1) * 4;
                float val = 0.f;
                if (nn < Nn) {
                    if (kk < 128) {
                        val = aggp[nn * 128 + kk];
                    } else {
                        val = selfp[nn * 128 + kk - 128];
                        if (layer == 2) {
                            val = fmaxf(fmaf(val, sm[SM_SCALE + kk - 128],
                                             sm[SM_SHIFT + kk - 128]), 0.f);
                        }
                    }
                }
                v[q] = val;
            }
            sA[i] = make_uint4(__float_as_uint(v[0]), __float_as_uint(v[1]),
                               __float_as_uint(v[2]), __float_as_uint(v[3]));
        }
        CP_WAIT0();
        __syncthreads();

        // ---- mma: 8 k8 steps; split A in registers; 2 precision sweeps ----
#pragma unroll 2
        for (int k8 = 0; k8 < 8; k8++) {
            uint4 ao = sA[(k8 * 4 + m16) * 32 + lane];
            float a0 = __uint_as_float(ao.x), a1 = __uint_as_float(ao.y);
            float a2 = __uint_as_float(ao.z), a3 = __uint_as_float(ao.w);
            float h0 = tf32r(a0), h1 = tf32r(a1), h2 = tf32r(a2), h3 = tf32r(a3);
            uint4 ah = make_uint4(__float_as_uint(h0), __float_as_uint(h1),
                                  __float_as_uint(h2), __float_as_uint(h3));
            uint4 al = make_uint4(__float_as_uint(tf32r(a0 - h0)),
                                  __float_as_uint(tf32r(a1 - h1)),
                                  __float_as_uint(tf32r(a2 - h2)),
                                  __float_as_uint(tf32r(a3 - h3)));
            uint4 bh[4];
#pragma unroll
            for (int pl = 0; pl < 4; pl++) {
                int p = fh * 4 + pl;
                bh[pl] = sB[(k8 * 8 + p) * 32 + lane];
            }
#pragma unroll
            for (int pl = 0; pl < 4; pl++) {
                mma1688(acc[2 * pl],     al, bh[pl].x, bh[pl].y);
                mma1688(acc[2 * pl + 1], al, bh[pl].z, bh[pl].w);
            }
#pragma unroll
            for (int pl = 0; pl < 4; pl++) {
                mma1688(acc[2 * pl],     ah, bh[pl].x, bh[pl].y);
                mma1688(acc[2 * pl + 1], ah, bh[pl].z, bh[pl].w);
            }
        }
    }

    // ---- epilogue: write D (and fp16 copy for layer-2 gather) ----
    int row0 = base + m16 * 16 + g;
    int row1 = row0 + 8;
#pragma unroll
    for (int a = 0; a < 8; a++) {
        int f0 = fh * 64 + a * 8 + 2 * tig;
        if (row0 < Nn) {
            *reinterpret_cast<float2*>(&outp[row0 * 128 + f0]) =
                make_float2(acc[a][0], acc[a][1]);
            if (layer == 1)
                *reinterpret_cast<__half2*>(&d_hh[row0 * 128 + f0]) =
                    __floats2half2_rn(acc[a][0], acc[a][1]);
        }
        if (row1 < Nn) {
            *reinterpret_cast<float2*>(&outp[row1 * 128 + f0]) =
                make_float2(acc[a][2], acc[a][3]);
            if (layer == 1)
                *reinterpret_cast<__half2*>(&d_hh[row1 * 128 + f0]) =
                    __floats2half2_rn(acc[a][2], acc[a][3]);
        }
    }
}

// ---------------- BN stats over pre-activations ----------------------------------
__global__ void k_bnstat(int layer) {
    const float* src = (layer == 1) ? (const float*)d_h : (const float*)d_agg;
    __shared__ float s1[128], s2[128];
    int tid = threadIdx.x;                 // 256
    if (tid < 128) { s1[tid] = 0.f; s2[tid] = 0.f; }
    __syncthreads();
    int f = tid & 127, h = tid >> 7;
    float a = 0.f, b = 0.f;
    for (int n = blockIdx.x * 2 + h; n < Nn; n += gridDim.x * 2) {
        float v = src[n * 128 + f];
        a += v; b += v * v;
    }
    atomicAdd(&s1[f], a);
    atomicAdd(&s2[f], b);
    __syncthreads();
    if (tid < 128) {
        atomicAdd(&d_sum[tid], s1[tid]);
        atomicAdd(&d_sqs[tid], s2[tid]);
    }
}

// ---------------- BN finalize (resets stats for next layer / replay) -------------
__global__ void k_bnfin(const float* __restrict__ g, const float* __restrict__ beta) {
    int fidx = threadIdx.x;
    float mu = d_sum[fidx] * (1.0f / Nn);
    float var = d_sqs[fidx] * (1.0f / Nn) - mu * mu;
    float sc = g[fidx] * rsqrtf(var + EPSBN);
    d_scale[fidx] = sc;
    d_shift[fidx] = beta[fidx] - mu * sc;
    d_sum[fidx] = 0.f;
    d_sqs[fidx] = 0.f;
}

// ---------------- fused norm+relu+pool: warp per node ----------------------------
__global__ void k_pool(const int* __restrict__ batch) {
    int n = (blockIdx.x * blockDim.x + threadIdx.x) >> 5;
    int lane = threadIdx.x & 31;
    if (n >= Nn) return;
    int b = batch[n];
    float4 v = reinterpret_cast<const float4*>(d_agg)[n * 32 + lane];
    float4 sc = reinterpret_cast<const float4*>(d_scale)[lane];
    float4 sh = reinterpret_cast<const float4*>(d_shift)[lane];
    v.x = fmaxf(fmaf(v.x, sc.x, sh.x), 0.f);
    v.y = fmaxf(fmaf(v.y, sc.y, sh.y), 0.f);
    v.z = fmaxf(fmaf(v.z, sc.z, sh.z), 0.f);
    v.w = fmaxf(fmaf(v.w, sc.w, sh.w), 0.f);
    float* pp = d_pool + b * 128 + lane * 4;
    asm volatile("red.global.add.v4.f32 [%0], {%1,%2,%3,%4};"
                 :: "l"(pp), "f"(v.x), "f"(v.y), "f"(v.z), "f"(v.w) : "memory");
    if (lane == 0) atomicAdd(d_cnt + b, 1.0f);
}

// ---------------- finalize (single block; self-cleans d_pool/d_cnt) --------------
__global__ void k_fin(float* __restrict__ out) {
    int tid = threadIdx.x;
    for (int i = tid; i < Bb * Ff; i += 1024) {
        float c = d_cnt[i >> 7];
        out[i] = d_pool[i] / fmaxf(c, 1.f);
    }
    __syncthreads();
    for (int i = tid; i < Bb * Ff; i += 1024) d_pool[i] = 0.f;
    if (tid < Bb) d_cnt[tid] = 0.f;
}

// ---------------- launcher --------------------------------------------------------
extern "C" void kernel_launch(void* const* d_in, const int* in_sizes, int n_in,
                              void* d_out, int out_size) {
    const float* x     = (const float*)d_in[0];
    const int*   ei    = (const int*)d_in[1];
    const int*   batch = (const int*)d_in[2];
    const float* wl1   = (const float*)d_in[3];
    const float* bl1   = (const float*)d_in[4];
    const float* wr1   = (const float*)d_in[5];
    const float* g1    = (const float*)d_in[6];
    const float* beta1 = (const float*)d_in[7];
    const float* wl2   = (const float*)d_in[8];
    const float* bl2   = (const float*)d_in[9];
    const float* wr2   = (const float*)d_in[10];
    const float* g2    = (const float*)d_in[11];
    const float* beta2 = (const float*)d_in[12];
    const int* src = ei;
    const int* dst = ei + Ee;
    float* out = (float*)d_out;

    cudaFuncSetAttribute(k_gemmT, cudaFuncAttributeMaxDynamicSharedMemorySize, SMEM_TB);

    const int edgeBlocks = (Ee + 255) / 256;
    const int gatherBlocks = (Nn * 32 + 255) / 256;
    const int prepBlocks = 256 + (Nn * 32 + 255) / 256;   // weights + x->fp16

    k_fillb<<<edgeBlocks, 256>>>(src, dst);                    // 0
    k_prep<<<prepBlocks, 256>>>(x, wl1, wr1, wl2, wr2);        // 1

    // ---- layer 1 ----
    k_gather<<<gatherBlocks, 256>>>(0, 0, 0);                  // 2
    k_gemmT<<<NT64, 256, SMEM_TB>>>(x, bl1, 1);                // 3  <- profiled
    k_bnstat<<<148, 256>>>(1);                                 // 4
    k_bnfin<<<1, 128>>>(g1, beta1);                            // 5

    // ---- layer 2 ----
    k_gather<<<gatherBlocks, 256>>>(1, 1, 1);                  // 6
    k_gemmT<<<NT64, 256, SMEM_TB>>>(x, bl2, 2);                // 7
    k_bnstat<<<148, 256>>>(2);                                 // 8
    k_bnfin<<<1, 128>>>(g2, beta2);                            // 9

    // ---- pool ----
    k_pool<<<(Nn + 7) / 8, 256>>>(batch);                      // 10
    k_fin<<<1, 1024>>>(out);                                   // 11
}

// round 15
// speedup vs baseline: 1.3255x; 1.0363x over previous
#include <cuda_runtime.h>
#include <cuda_fp16.h>
#include <cstdint>

#define Nn 50000
#define Ee 800000
#define Ff 128
#define Bb 64
#define EPSBN 1e-5f
#define DEGCAP 64
#define NT64 782              // ceil(50000/64)

// ---------------- device scratch (zero-init; self-cleaning for graph replay) ----
__device__ __align__(16) float d_agg[Nn * Ff];   // mean-agg; layer2 GEMM writes pre2 here
__device__ __align__(16) float d_h[Nn * Ff];     // pre1 fp32 (pre-BN)
__device__ __align__(16) __half d_xh[Nn * Ff];   // fp16 copy of x (gather input)
__device__ __align__(16) __half d_hh[Nn * Ff];   // fp16 copy of pre1 (gather-2 input)
__device__ int   d_cnt_i[Nn];                    // degree; re-zeroed by layer-2 gather
__device__ int   d_esrc[Nn * DEGCAP];            // bucket adjacency
__device__ float d_sum[Ff];                      // re-zeroed by k_bnfin
__device__ float d_sqs[Ff];
__device__ __align__(16) float d_scale[Ff];
__device__ __align__(16) float d_shift[Ff];
__device__ __align__(16) float d_pool[Bb * Ff];  // re-zeroed by k_fin
__device__ float d_cnt[Bb];                      // re-zeroed by k_fin
// prepacked weight fragments (mma register order), tf32 hi only: [layer][32768]
__device__ __align__(16) float d_wfh[2][32768];

// ---------------- helpers ----------------
__device__ __forceinline__ uint32_t smem_u32(const void* p) {
    uint32_t a;
    asm("{ .reg .u64 t; cvta.to.shared.u64 t, %1; cvt.u32.u64 %0, t; }" : "=r"(a) : "l"(p));
    return a;
}
__device__ __forceinline__ float tf32r(float x) {
    uint32_t u;
    asm("cvt.rna.tf32.f32 %0, %1;" : "=r"(u) : "f"(x));
    return __uint_as_float(u);
}
__device__ __forceinline__ void mma1688(float* c, const uint4 a, const uint32_t b0, const uint32_t b1) {
    asm volatile("mma.sync.aligned.m16n8k8.row.col.f32.tf32.tf32.f32 "
        "{%0,%1,%2,%3}, {%4,%5,%6,%7}, {%8,%9}, {%0,%1,%2,%3};"
        : "+f"(c[0]), "+f"(c[1]), "+f"(c[2]), "+f"(c[3])
        : "r"(a.x), "r"(a.y), "r"(a.z), "r"(a.w), "r"(b0), "r"(b1));
}
#define CP_ASYNC16(sdst, gsrc) \
    asm volatile("cp.async.ca.shared.global [%0], [%1], 16;" :: "r"(sdst), "l"(gsrc) : "memory")
#define CP_COMMIT() asm volatile("cp.async.commit_group;" ::: "memory")
#define CP_WAIT0()  asm volatile("cp.async.wait_group 0;" ::: "memory")

// ---------------- bucket adjacency build ----------------
__global__ void k_fillb(const int* __restrict__ src, const int* __restrict__ dst) {
    int e = blockIdx.x * blockDim.x + threadIdx.x;
    if (e < Ee) {
        int d = dst[e];
        int pos = atomicAdd(&d_cnt_i[d], 1);
        if (pos < DEGCAP) d_esrc[d * DEGCAP + pos] = src[e];
    }
}

// ---------------- prep: weight fragments (tf32 hi) + fp16 copy of x --------------
__global__ void k_prep(const float* __restrict__ x,
                       const float* __restrict__ wl1, const float* __restrict__ wr1,
                       const float* __restrict__ wl2, const float* __restrict__ wr2) {
    int gid = blockIdx.x * 256 + threadIdx.x;
    if (blockIdx.x < 256) {
        int idx = gid;                  // 0..65535
        int layer = idx >> 15;
        int rem = idx & 32767;
        int pos = rem >> 2;
        int j = rem & 3;
        int K8 = pos >> 8;
        int p = (pos >> 5) & 7;
        int lane = pos & 31;
        int n8 = 2 * p + (j >> 1);
        int f = n8 * 8 + (lane >> 2);
        int k = K8 * 8 + (lane & 3) + (j & 1) * 4;
        const float* wl = layer ? wl2 : wl1;
        const float* wr = layer ? wr2 : wr1;
        float w = (k < 128) ? wl[k * 128 + f] : wr[(k - 128) * 128 + f];
        d_wfh[layer][rem] = tf32r(w);
    } else {
        int i = gid - 65536;            // float4 index into x
        if (i < Nn * 32) {
            float4 v = reinterpret_cast<const float4*>(x)[i];
            __half2* o = reinterpret_cast<__half2*>(d_xh) + 2 * i;
            o[0] = __floats2half2_rn(v.x, v.y);
            o[1] = __floats2half2_rn(v.z, v.w);
        }
    }
}

// ---------------- pull gather (fp16 inputs): warp per node, mean aggregation -----
__global__ void k_gather(int useH, int norm, int clearCnt) {
    int n = (blockIdx.x * blockDim.x + threadIdx.x) >> 5;
    int lane = threadIdx.x & 31;
    if (n >= Nn) return;
    const __half* feat = useH ? d_hh : d_xh;
    const uint2* f2 = reinterpret_cast<const uint2*>(feat);   // 32 uint2 per row
    const int deg = d_cnt_i[n];
    const int m = deg < DEGCAP ? deg : DEGCAP;
    const int* eb = d_esrc + n * DEGCAP;
    float4 acc = make_float4(0.f, 0.f, 0.f, 0.f);
    float4 sc, sh;
    if (norm) {
        sc = reinterpret_cast<const float4*>(d_scale)[lane];
        sh = reinterpret_cast<const float4*>(d_shift)[lane];
    }
#define CV4(u, v) { \
        __half2 _ha = *reinterpret_cast<__half2*>(&(u).x); \
        __half2 _hb = *reinterpret_cast<__half2*>(&(u).y); \
        float2 _pa = __half22float2(_ha); \
        float2 _pb = __half22float2(_hb); \
        v = make_float4(_pa.x, _pa.y, _pb.x, _pb.y); }
#define NORM4(v) if (norm) { \
        v.x = fmaxf(fmaf(v.x, sc.x, sh.x), 0.f); v.y = fmaxf(fmaf(v.y, sc.y, sh.y), 0.f); \
        v.z = fmaxf(fmaf(v.z, sc.z, sh.z), 0.f); v.w = fmaxf(fmaf(v.w, sc.w, sh.w), 0.f); }
    int j = 0;
    // 16-wide pass: maximize loads in flight (latency-bound for typical deg~16)
    for (; j + 16 <= m; j += 16) {
        uint2 u[16];
#pragma unroll
        for (int q = 0; q < 16; q++) u[q] = f2[eb[j + q] * 32 + lane];
#pragma unroll
        for (int q = 0; q < 16; q++) {
            float4 v;
            CV4(u[q], v)
            NORM4(v)
            acc.x += v.x; acc.y += v.y; acc.z += v.z; acc.w += v.w;
        }
    }
    for (; j + 8 <= m; j += 8) {
        uint2 u[8];
#pragma unroll
        for (int q = 0; q < 8; q++) u[q] = f2[eb[j + q] * 32 + lane];
#pragma unroll
        for (int q = 0; q < 8; q++) {
            float4 v;
            CV4(u[q], v)
            NORM4(v)
            acc.x += v.x; acc.y += v.y; acc.z += v.z; acc.w += v.w;
        }
    }
    for (; j < m; j++) {
        uint2 u0 = f2[eb[j] * 32 + lane];
        float4 v0;
        CV4(u0, v0)
        NORM4(v0)
        acc.x += v0.x; acc.y += v0.y; acc.z += v0.z; acc.w += v0.w;
    }
#undef NORM4
#undef CV4
    float inv = 1.f / fmaxf((float)deg, 1.f);
    acc.x *= inv; acc.y *= inv; acc.z *= inv; acc.w *= inv;
    reinterpret_cast<float4*>(d_agg)[n * 32 + lane] = acc;
    if (clearCnt && lane == 0) d_cnt_i[n] = 0;
}

// ---------------- tensor-core dual GEMM + fused BN stats -------------------------
// D = (Ah + Al) * Bh (tf32 split in registers). BN sum/sumsq accumulated in the
// epilogue via smem atomics, flushed with one global atomic per feature per CTA.
// CTA tile = 64 nodes x 128 feats; smem ~50KB -> 3 CTAs/SM. One tile per CTA.
// smem float offsets
#define SM_BIAS  0
#define SM_SCALE 128
#define SM_SHIFT 256
#define SM_SUM   384
#define SM_SQ    512
#define SM_A     640
#define SM_B     (640 + 4096)
#define SMEM_TFL (640 + 12288)
#define SMEM_TB  (SMEM_TFL * 4)

__global__ void __launch_bounds__(256, 3)
k_gemmT(const float* __restrict__ xin, const float* __restrict__ bias, int layer) {
    extern __shared__ float sm[];
    uint4* sA = reinterpret_cast<uint4*>(sm + SM_A);
    uint4* sB = reinterpret_cast<uint4*>(sm + SM_B);

    const int tid = threadIdx.x;
    const int lane = tid & 31;
    const int w = tid >> 5;
    const int m16 = w & 3;            // node 16-block within tile
    const int fh  = w >> 2;           // feature half
    const int g = lane >> 2;
    const int tig = lane & 3;

    const float* aggp  = (const float*)d_agg;
    const float* selfp = (layer == 1) ? xin : (const float*)d_h;
    float* outp = (layer == 1) ? (float*)d_h : (float*)d_agg;
    const float* gbh = d_wfh[layer - 1];

    if (tid < 128) {
        sm[SM_BIAS + tid]  = bias[tid];
        sm[SM_SCALE + tid] = d_scale[tid];
        sm[SM_SHIFT + tid] = d_shift[tid];
        sm[SM_SUM + tid] = 0.f;
        sm[SM_SQ + tid]  = 0.f;
    }

    const int base = blockIdx.x * 64;

    float acc[8][4];
    __syncthreads();
#pragma unroll
    for (int a = 0; a < 8; a++) {
        int f0 = fh * 64 + a * 8 + 2 * tig;
        float b0 = sm[SM_BIAS + f0];
        float b1 = sm[SM_BIAS + f0 + 1];
        acc[a][0] = b0; acc[a][1] = b1;
        acc[a][2] = b0; acc[a][3] = b1;
    }

    const uint32_t sBaddr = smem_u32(sB);

    for (int c = 0; c < 4; c++) {
        __syncthreads();
        // ---- B fragments via cp.async (raw copy, 8192 floats) ----
        {
            const float4* gh4 = reinterpret_cast<const float4*>(gbh + c * 8192);
            for (int i = tid; i < 2048; i += 256) {
                CP_ASYNC16(sBaddr + i * 16, (const void*)(gh4 + i));
            }
            CP_COMMIT();
        }
        // ---- stage A raw fp32 fragments: 1024 slots (k8[8], m16[4], lane[32]) ----
        for (int i = tid; i < 1024; i += 256) {
            int lp  = i & 31;
            int mm  = (i >> 5) & 3;
            int k8  = i >> 7;
            int n0 = base + mm * 16 + (lp >> 2);
            int kg = c * 64 + k8 * 8 + (lp & 3);
            float v[4];
#pragma unroll
            for (int q = 0; q < 4; q++) {
                int nn = n0 + (q & 1) * 8;
                int kk = kg + (q >> 1) * 4;
                float val = 0.f;
                if (nn < Nn) {
                    if (kk < 128) {
                        val = aggp[nn * 128 + kk];
                    } else {
                        val = selfp[nn * 128 + kk - 128];
                        if (layer == 2) {
                            val = fmaxf(fmaf(val, sm[SM_SCALE + kk - 128],
                                             sm[SM_SHIFT + kk - 128]), 0.f);
                        }
                    }
                }
                v[q] = val;
            }
            sA[i] = make_uint4(__float_as_uint(v[0]), __float_as_uint(v[1]),
                               __float_as_uint(v[2]), __float_as_uint(v[3]));
        }
        CP_WAIT0();
        __syncthreads();

        // ---- mma: 8 k8 steps; split A in registers; 2 precision sweeps ----
#pragma unroll 2
        for (int k8 = 0; k8 < 8; k8++) {
            uint4 ao = sA[(k8 * 4 + m16) * 32 + lane];
            float a0 = __uint_as_float(ao.x), a1 = __uint_as_float(ao.y);
            float a2 = __uint_as_float(ao.z), a3 = __uint_as_float(ao.w);
            float h0 = tf32r(a0), h1 = tf32r(a1), h2 = tf32r(a2), h3 = tf32r(a3);
            uint4 ah = make_uint4(__float_as_uint(h0), __float_as_uint(h1),
                                  __float_as_uint(h2), __float_as_uint(h3));
            uint4 al = make_uint4(__float_as_uint(tf32r(a0 - h0)),
                                  __float_as_uint(tf32r(a1 - h1)),
                                  __float_as_uint(tf32r(a2 - h2)),
                                  __float_as_uint(tf32r(a3 - h3)));
            uint4 bh[4];
#pragma unroll
            for (int pl = 0; pl < 4; pl++) {
                int p = fh * 4 + pl;
                bh[pl] = sB[(k8 * 8 + p) * 32 + lane];
            }
#pragma unroll
            for (int pl = 0; pl < 4; pl++) {
                mma1688(acc[2 * pl],     al, bh[pl].x, bh[pl].y);
                mma1688(acc[2 * pl + 1], al, bh[pl].z, bh[pl].w);
            }
#pragma unroll
            for (int pl = 0; pl < 4; pl++) {
                mma1688(acc[2 * pl],     ah, bh[pl].x, bh[pl].y);
                mma1688(acc[2 * pl + 1], ah, bh[pl].z, bh[pl].w);
            }
        }
    }

    // ---- epilogue: write D (+fp16 copy for layer-2 gather) + BN stats ----
    int row0 = base + m16 * 16 + g;
    int row1 = row0 + 8;
#pragma unroll
    for (int a = 0; a < 8; a++) {
        int f0 = fh * 64 + a * 8 + 2 * tig;
        float s0 = 0.f, s1 = 0.f, q0 = 0.f, q1 = 0.f;
        if (row0 < Nn) {
            *reinterpret_cast<float2*>(&outp[row0 * 128 + f0]) =
                make_float2(acc[a][0], acc[a][1]);
            if (layer == 1)
                *reinterpret_cast<__half2*>(&d_hh[row0 * 128 + f0]) =
                    __floats2half2_rn(acc[a][0], acc[a][1]);
            s0 += acc[a][0]; q0 += acc[a][0] * acc[a][0];
            s1 += acc[a][1]; q1 += acc[a][1] * acc[a][1];
        }
        if (row1 < Nn) {
            *reinterpret_cast<float2*>(&outp[row1 * 128 + f0]) =
                make_float2(acc[a][2], acc[a][3]);
            if (layer == 1)
                *reinterpret_cast<__half2*>(&d_hh[row1 * 128 + f0]) =
                    __floats2half2_rn(acc[a][2], acc[a][3]);
            s0 += acc[a][2]; q0 += acc[a][2] * acc[a][2];
            s1 += acc[a][3]; q1 += acc[a][3] * acc[a][3];
        }
        atomicAdd(&sm[SM_SUM + f0], s0);
        atomicAdd(&sm[SM_SUM + f0 + 1], s1);
        atomicAdd(&sm[SM_SQ + f0], q0);
        atomicAdd(&sm[SM_SQ + f0 + 1], q1);
    }
    __syncthreads();
    if (tid < 128) {
        atomicAdd(&d_sum[tid], sm[SM_SUM + tid]);
        atomicAdd(&d_sqs[tid], sm[SM_SQ + tid]);
    }
}

// ---------------- BN finalize (resets stats for next layer / replay) -------------
__global__ void k_bnfin(const float* __restrict__ g, const float* __restrict__ beta) {
    int fidx = threadIdx.x;
    float mu = d_sum[fidx] * (1.0f / Nn);
    float var = d_sqs[fidx] * (1.0f / Nn) - mu * mu;
    float sc = g[fidx] * rsqrtf(var + EPSBN);
    d_scale[fidx] = sc;
    d_shift[fidx] = beta[fidx] - mu * sc;
    d_sum[fidx] = 0.f;
    d_sqs[fidx] = 0.f;
}

// ---------------- fused norm+relu+pool: warp per node ----------------------------
__global__ void k_pool(const int* __restrict__ batch) {
    int n = (blockIdx.x * blockDim.x + threadIdx.x) >> 5;
    int lane = threadIdx.x & 31;
    if (n >= Nn) return;
    int b = batch[n];
    float4 v = reinterpret_cast<const float4*>(d_agg)[n * 32 + lane];
    float4 sc = reinterpret_cast<const float4*>(d_scale)[lane];
    float4 sh = reinterpret_cast<const float4*>(d_shift)[lane];
    v.x = fmaxf(fmaf(v.x, sc.x, sh.x), 0.f);
    v.y = fmaxf(fmaf(v.y, sc.y, sh.y), 0.f);
    v.z = fmaxf(fmaf(v.z, sc.z, sh.z), 0.f);
    v.w = fmaxf(fmaf(v.w, sc.w, sh.w), 0.f);
    float* pp = d_pool + b * 128 + lane * 4;
    asm volatile("red.global.add.v4.f32 [%0], {%1,%2,%3,%4};"
                 :: "l"(pp), "f"(v.x), "f"(v.y), "f"(v.z), "f"(v.w) : "memory");
    if (lane == 0) atomicAdd(d_cnt + b, 1.0f);
}

// ---------------- finalize (single block; self-cleans d_pool/d_cnt) --------------
__global__ void k_fin(float* __restrict__ out) {
    int tid = threadIdx.x;
    for (int i = tid; i < Bb * Ff; i += 1024) {
        float c = d_cnt[i >> 7];
        out[i] = d_pool[i] / fmaxf(c, 1.f);
    }
    __syncthreads();
    for (int i = tid; i < Bb * Ff; i += 1024) d_pool[i] = 0.f;
    if (tid < Bb) d_cnt[tid] = 0.f;
}

// ---------------- launcher --------------------------------------------------------
extern "C" void kernel_launch(void* const* d_in, const int* in_sizes, int n_in,
                              void* d_out, int out_size) {
    const float* x     = (const float*)d_in[0];
    const int*   ei    = (const int*)d_in[1];
    const int*   batch = (const int*)d_in[2];
    const float* wl1   = (const float*)d_in[3];
    const float* bl1   = (const float*)d_in[4];
    const float* wr1   = (const float*)d_in[5];
    const float* g1    = (const float*)d_in[6];
    const float* beta1 = (const float*)d_in[7];
    const float* wl2   = (const float*)d_in[8];
    const float* bl2   = (const float*)d_in[9];
    const float* wr2   = (const float*)d_in[10];
    const float* g2    = (const float*)d_in[11];
    const float* beta2 = (const float*)d_in[12];
    const int* src = ei;
    const int* dst = ei + Ee;
    float* out = (float*)d_out;

    cudaFuncSetAttribute(k_gemmT, cudaFuncAttributeMaxDynamicSharedMemorySize, SMEM_TB);

    const int edgeBlocks = (Ee + 255) / 256;
    const int gatherBlocks = (Nn * 32 + 255) / 256;
    const int prepBlocks = 256 + (Nn * 32 + 255) / 256;

    k_fillb<<<edgeBlocks, 256>>>(src, dst);                    // 0
    k_prep<<<prepBlocks, 256>>>(x, wl1, wr1, wl2, wr2);        // 1

    // ---- layer 1 ----
    k_gather<<<gatherBlocks, 256>>>(0, 0, 0);                  // 2
    k_gemmT<<<NT64, 256, SMEM_TB>>>(x, bl1, 1);                // 3  <- profiled
    k_bnfin<<<1, 128>>>(g1, beta1);                            // 4

    // ---- layer 2 ----
    k_gather<<<gatherBlocks, 256>>>(1, 1, 1);                  // 5
    k_gemmT<<<NT64, 256, SMEM_TB>>>(x, bl2, 2);                // 6
    k_bnfin<<<1, 128>>>(g2, beta2);                            // 7

    // ---- pool ----
    k_pool<<<(Nn + 7) / 8, 256>>>(batch);                      // 8
    k_fin<<<1, 1024>>>(out);                                   // 9
}